// round 12
// baseline (speedup 1.0000x reference)
#include <cuda_runtime.h>
#include <cuda_fp16.h>
#include <cstdint>

// Problem constants
#define NQ      16384      // B*H*W
#define NEG     4096       // embeddings per group
#define GR      4
#define KD      64         // embedding dim
#define TQ      128        // queries per block
#define NT      128        // e per tile
#define NTILES  32         // tiles per group
#define EHT     21         // HMMA tiles  (e in [0, 2688))
#define EDT     11         // dp4a tiles  (e in [2688, 4096))
#define CAP     64         // candidate capacity per row

#define QUANT_SZ 4194304ULL
#define ME_OFFC  4194317ULL   // QUANT_SZ + 13 (odd -> unaligned head)

typedef unsigned long long ull;

// ---- device scratch (static, no allocation) ----
__device__ int      g_idx[NQ * GR];               // final argmax indices
__device__ float    g_embn[NEG * GR * KD];        // normalized embedding (fp32)
__device__ int      g_embh[GR * NTILES * 4096];   // fp16 swizzled 16KB tile images
__device__ int      g_embq[GR * NTILES * 2048];   // int8 packed [tile][k4][e] images
__device__ int      g_hist[NEG];                  // histogram of idx[:, 3]
__device__ int      g_cnt[NQ * GR];               // candidate counts
__device__ int      g_cand[NQ * GR * CAP];        // candidate e-indices

// ============================================================================
// PTX helpers (base-target: ldmatrix sm_75+, mma.sync sm_80+)
// ============================================================================
__device__ __forceinline__ uint32_t smem_u32(const void* p) {
    uint32_t a;
    asm("{ .reg .u64 t; cvta.to.shared.u64 t, %1; cvt.u32.u64 %0, t; }"
        : "=r"(a) : "l"(p));
    return a;
}
#define LDSM_X4(r, addr) \
    asm volatile("ldmatrix.sync.aligned.m8n8.x4.shared.b16 {%0,%1,%2,%3}, [%4];" \
        : "=r"((r)[0]), "=r"((r)[1]), "=r"((r)[2]), "=r"((r)[3]) : "r"(addr))

__device__ __forceinline__ void mma16816(float* c, const uint32_t* a,
                                         const uint32_t* b) {
    asm volatile("mma.sync.aligned.m16n8k16.row.col.f32.f16.f16.f32 "
        "{%0,%1,%2,%3}, {%4,%5,%6,%7}, {%8,%9}, {%0,%1,%2,%3};"
        : "+f"(c[0]), "+f"(c[1]), "+f"(c[2]), "+f"(c[3])
        : "r"(a[0]), "r"(a[1]), "r"(a[2]), "r"(a[3]), "r"(b[0]), "r"(b[1]));
}
#define BAR_H() asm volatile("bar.sync 1, 256;" ::: "memory")
#define BAR_D() asm volatile("bar.sync 2, 256;" ::: "memory")

// ============================================================================
// emb prep (+ counter init folded): normalize -> g_embn; fp16 swizzled
// images -> g_embh; int8 x126 packed [k4][e] images -> g_embq.
// One warp per embedding row; 2048 x 256 launch (16384 warps exactly).
// ============================================================================
__global__ void embprep_kernel(const float* __restrict__ emb)
{
    int gidx = blockIdx.x * blockDim.x + threadIdx.x;
    if (gidx < NQ * GR) g_cnt[gidx] = 0;
    if (gidx < NEG)     g_hist[gidx] = 0;

    int warp = gidx >> 5;
    int lane = threadIdx.x & 31;
    float2 v = reinterpret_cast<const float2*>(emb + (size_t)warp * KD)[lane];
    float s = v.x * v.x + v.y * v.y;
    #pragma unroll
    for (int m = 16; m >= 1; m >>= 1) s += __shfl_xor_sync(0xffffffffu, s, m);
    float inv = 1.0f / fmaxf(sqrtf(s), 1e-12f);
    float2 o = make_float2(v.x * inv, v.y * inv);
    reinterpret_cast<float2*>(g_embn + (size_t)warp * KD)[lane] = o;

    int g  = warp >> 12;
    int el = warp & 4095;
    int et = el >> 7, er = el & 127;

    // fp16 swizzled image
    __half2 h2 = __floats2half2_rn(o.x, o.y);
    int w; memcpy(&w, &h2, 4);
    int ui = er * 32 + ((((lane >> 2)) ^ (er & 7)) << 2) + (lane & 3);
    g_embh[(size_t)(g * NTILES + et) * 4096 + ui] = w;

    // int8 packed image: word k4 covers coords 4k4..4k4+3
    int q0 = __float2int_rn(o.x * 126.0f);
    int q1 = __float2int_rn(o.y * 126.0f);
    int hf = (q0 & 0xFF) | ((q1 & 0xFF) << 8);
    int lo = __shfl_sync(0xffffffffu, hf, (lane & 15) * 2);
    int hi = __shfl_sync(0xffffffffu, hf, (lane & 15) * 2 + 1);
    if (lane < 16)
        g_embq[((size_t)(g * NTILES + et) * 16 + lane) * 128 + er] =
            (lo & 0xFFFF) | (hi << 16);
}

// ============================================================================
// Dual-engine argmax: 512 threads, 1 CTA/SM.
// threads [0,256)   = HMMA engine (R8 core), e tiles 0..EHT-1, zero-stores.
// threads [256,512) = dp4a engine (R2 core), e tiles EHT..31.
// Disjoint registers, disjoint named barriers; shared prologue builds both
// A images + margins + zmax.
// Smem: smarg[128]@0 | sn2[512]@512 | sred@2560 | A_fp16 16KB@3072 |
//   A_int8 8KB@19456 | Bh0@27648 Bh1@44032 (16KB) | Bd0@60416 Bd1@68608 (8KB)
//   total 76800.
// ============================================================================
__global__ __launch_bounds__(512, 1)
void vq_dual_kernel(const float* __restrict__ z, float* __restrict__ out)
{
    extern __shared__ __align__(1024) char smem[];
    float* smarg = reinterpret_cast<float*>(smem);            // 128 floats
    float* sn2   = reinterpret_cast<float*>(smem + 512);      // 512 floats
    float* sred  = reinterpret_cast<float*>(smem + 2560);     // 17 floats
    uint32_t sbase = smem_u32(smem);
    const uint32_t aA = sbase + 3072;
    const uint32_t aBh[2] = { sbase + 27648, sbase + 44032 };
    int4* sBh4[2] = { reinterpret_cast<int4*>(smem + 27648),
                      reinterpret_cast<int4*>(smem + 44032) };
    int*  A8w   = reinterpret_cast<int*>(smem + 19456);
    int*  Bd[2] = { reinterpret_cast<int*>(smem + 60416),
                    reinterpret_cast<int*>(smem + 68608) };

    const int tid   = threadIdx.x;
    const int item  = blockIdx.x;
    const int g     = item & 3;
    const int qbase = (item >> 2) * TQ;

    // ---- shared prologue: A images (fp16 + int8), margins, zmax ----
    const int q  = tid & 127;
    const int ph = tid >> 7;                 // 0..3, covers c = ph*16..+15
    float v[16];
    {
        const int b   = qbase >> 10;
        const int hwb = qbase & 1023;
        const float* zb = z + (size_t)b * 262144 + (size_t)(g * 64) * 1024 + hwb;
        __half2* A2 = reinterpret_cast<__half2*>(smem + 3072);
        float n2 = 0.0f, zm = 0.0f;
        #pragma unroll
        for (int i = 0; i < 16; i++) {
            int c = ph * 16 + i;
            float vv = zb[(size_t)c * 1024 + q];
            v[i] = vv;
            n2 += vv * vv;
            zm = fmaxf(zm, fabsf(vv));
        }
        // fp16 image (8 half2 per thread)
        #pragma unroll
        for (int j = 0; j < 8; j++) {
            int c = ph * 16 + 2 * j;
            int ui = q * 32 + (((c >> 3) ^ (q & 7)) << 2) + ((c & 7) >> 1);
            A2[ui] = __floats2half2_rn(v[2 * j], v[2 * j + 1]);
        }
        sn2[q * 4 + ph] = n2;
        unsigned um = __reduce_max_sync(0xffffffffu, __float_as_uint(zm));
        if ((tid & 31) == 0) sred[tid >> 5] = __uint_as_float(um);
        // preload Bh(0): 16KB by 512 threads (2 int4), Bd(0): 8KB (1 int4)
        {
            const int4* sh = reinterpret_cast<const int4*>(
                g_embh + (size_t)(g * NTILES) * 4096);
            sBh4[0][tid]       = sh[tid];
            sBh4[0][tid + 512] = sh[tid + 512];
            const int4* sd = reinterpret_cast<const int4*>(
                g_embq + (size_t)(g * NTILES + EHT) * 2048);
            reinterpret_cast<int4*>(Bd[0])[tid] = sd[tid];
        }
        __syncthreads();
        if (tid < 128)
            smarg[tid] = 0.006f * sqrtf(sn2[tid * 4] + sn2[tid * 4 + 1] +
                                        sn2[tid * 4 + 2] + sn2[tid * 4 + 3]);
        if (tid == 0) {
            float m = sred[0];
            #pragma unroll
            for (int i = 1; i < 16; i++) m = fmaxf(m, sred[i]);
            sred[16] = fmaxf(m, 1e-12f);
        }
        __syncthreads();
    }
    const float sz = 126.0f / sred[16];
    const int marg_i = (int)(0.25f * sz * 126.0f) + 2;
    // int8 A image: 4 words per thread (k4 = ph*4 + w)
    #pragma unroll
    for (int w = 0; w < 4; w++) {
        int word = 0;
        #pragma unroll
        for (int j = 0; j < 4; j++) {
            int qv = __float2int_rn(v[w * 4 + j] * sz);
            word |= (qv & 0xFF) << (j * 8);
        }
        A8w[(ph * 4 + w) * 128 + q] = word;
    }
    __syncthreads();

    if (tid < 256) {
        // ================= HMMA engine (R8 core), tiles 0..EHT-1 ==========
        const int w  = tid >> 5;
        const int l  = tid & 31;
        const int qw = (w & 3) * 32;
        const int ew = (w >> 2) * 64;
        float rm[4], marg[4];
        int   rowg[4];
        #pragma unroll
        for (int qb = 0; qb < 2; qb++)
            #pragma unroll
            for (int h = 0; h < 2; h++) {
                int slot = qb * 2 + h;
                int rq = qw + qb * 16 + (l >> 2) + h * 8;
                rm[slot]   = -3.0e38f;
                marg[slot] = smarg[rq];
                rowg[slot] = (qbase + rq) * GR + g;
            }
        const int4* ehsrc = reinterpret_cast<const int4*>(
            g_embh + (size_t)(g * NTILES) * 4096);
        const size_t S = ME_OFFC + (size_t)item * 131072;
        float4* me4 = reinterpret_cast<float4*>(out + S + 3);
        if (tid < 3)  out[S + tid] = 0.0f;
        if (tid == 3) out[S + 131071] = 0.0f;

        for (int t = 0; t < EHT; t++) {
            if (t + 1 < EHT) {
                const int4* s4 = ehsrc + (size_t)(t + 1) * 1024;
                int4* d4 = sBh4[(t + 1) & 1];
                #pragma unroll
                for (int i = 0; i < 4; i++) d4[tid + i * 256] = s4[tid + i * 256];
            }
            // zero-store chunk of min_encodings slice (tensor-bound side)
            {
                const float4 z4 = make_float4(0.f, 0.f, 0.f, 0.f);
                #pragma unroll
                for (int i = 0; i < 7; i++) {
                    int j = (t * 7 + i) * 256 + tid;
                    if (j < 32767) me4[j] = z4;
                }
            }
            float acc[2][8][4];
            #pragma unroll
            for (int qb = 0; qb < 2; qb++)
                #pragma unroll
                for (int eb = 0; eb < 8; eb++)
                    #pragma unroll
                    for (int j = 0; j < 4; j++) acc[qb][eb][j] = 0.0f;

            const uint32_t base = aBh[t & 1];
            #pragma unroll
            for (int ks = 0; ks < 4; ks++) {
                uint32_t RA[2][4];
                #pragma unroll
                for (int qb = 0; qb < 2; qb++) {
                    int row = qw + qb * 16 + (l & 15);
                    int blk = ks * 2 + (l >> 4);
                    LDSM_X4(RA[qb], aA + row * 128 + ((blk ^ (row & 7)) << 4));
                }
                uint32_t RB[4][4];
                #pragma unroll
                for (int ebp = 0; ebp < 4; ebp++) {
                    int row = ew + ebp * 16 + (l & 7) + ((l >> 4) << 3);
                    int blk = ks * 2 + ((l >> 3) & 1);
                    LDSM_X4(RB[ebp], base + row * 128 + ((blk ^ (row & 7)) << 4));
                }
                #pragma unroll
                for (int qb = 0; qb < 2; qb++)
                    #pragma unroll
                    for (int eb = 0; eb < 8; eb++)
                        mma16816(acc[qb][eb], RA[qb], &RB[eb >> 1][(eb & 1) * 2]);
            }
            // epilogue: half2 max tree + gated scan
            #pragma unroll
            for (int qb = 0; qb < 2; qb++)
                #pragma unroll
                for (int h = 0; h < 2; h++) {
                    const int slot = qb * 2 + h;
                    __half2 m2 = __floats2half2_rn(acc[qb][0][h * 2],
                                                   acc[qb][0][h * 2 + 1]);
                    #pragma unroll
                    for (int eb = 1; eb < 8; eb++)
                        m2 = __hmax2(m2, __floats2half2_rn(acc[qb][eb][h * 2],
                                                           acc[qb][eb][h * 2 + 1]));
                    float mx = __half2float(__hmax(__low2half(m2),
                                                   __high2half(m2)));
                    mx = fmaxf(mx, __shfl_xor_sync(0xffffffffu, mx, 1));
                    mx = fmaxf(mx, __shfl_xor_sync(0xffffffffu, mx, 2));
                    if (mx > rm[slot]) rm[slot] = mx;
                    const float thr = rm[slot] - marg[slot];
                    if (__any_sync(0xffffffffu, mx >= thr - 0.015f)) {
                        #pragma unroll
                        for (int eb = 0; eb < 8; eb++)
                            #pragma unroll
                            for (int j = 0; j < 2; j++) {
                                float vv = acc[qb][eb][h * 2 + j];
                                if (vv >= thr) {
                                    int sc = atomicAdd(&g_cnt[rowg[slot]], 1);
                                    if (sc < CAP)
                                        g_cand[(size_t)rowg[slot] * CAP + sc] =
                                            t * NT + ew + eb * 8 +
                                            (l & 3) * 2 + j;
                                }
                            }
                    }
                }
            BAR_H();
        }
    } else {
        // ================= dp4a engine (R2 core), tiles EHT..31 ===========
        const int tid2 = tid - 256;
        const int ty = tid2 >> 4;     // q rows ty*8..+7
        const int tx = tid2 & 15;     // e cols tx*8..+7
        int rm_i[8];
        #pragma unroll
        for (int i = 0; i < 8; i++) rm_i[i] = (int)0x80000000;
        const int* edsrc = g_embq + (size_t)(g * NTILES) * 2048;

        for (int t = 0; t < EDT; t++) {
            if (t + 1 < EDT) {
                const int4* s4 = reinterpret_cast<const int4*>(
                    edsrc + (size_t)(EHT + t + 1) * 2048);
                int4* d4 = reinterpret_cast<int4*>(Bd[(t + 1) & 1]);
                d4[tid2]       = s4[tid2];
                d4[tid2 + 256] = s4[tid2 + 256];
            }
            const int* bb_ = Bd[t & 1];
            int acc[8][8];
            #pragma unroll
            for (int i = 0; i < 8; i++)
                #pragma unroll
                for (int j = 0; j < 8; j++) acc[i][j] = 0;
            #pragma unroll 4
            for (int k4 = 0; k4 < 16; k4++) {
                int a[8], b[8];
                #pragma unroll
                for (int i = 0; i < 8; i++) a[i] = A8w[k4 * 128 + ty * 8 + i];
                #pragma unroll
                for (int j = 0; j < 8; j++) b[j] = bb_[k4 * 128 + tx * 8 + j];
                #pragma unroll
                for (int i = 0; i < 8; i++)
                    #pragma unroll
                    for (int j = 0; j < 8; j++)
                        acc[i][j] = __dp4a(a[i], b[j], acc[i][j]);
            }
            #pragma unroll
            for (int i = 0; i < 8; i++) {
                int m = acc[i][0];
                #pragma unroll
                for (int j = 1; j < 8; j++) m = max(m, acc[i][j]);
                #pragma unroll
                for (int o = 8; o >= 1; o >>= 1)
                    m = max(m, __shfl_xor_sync(0xffffffffu, m, o, 16));
                rm_i[i] = max(rm_i[i], m);
                const int thr = rm_i[i] - marg_i;
                if (__any_sync(0xffffffffu, m >= thr)) {
                    const int row = (qbase + ty * 8 + i) * GR + g;
                    #pragma unroll
                    for (int j = 0; j < 8; j++) {
                        if (acc[i][j] >= thr) {
                            int sc = atomicAdd(&g_cnt[row], 1);
                            if (sc < CAP)
                                g_cand[(size_t)row * CAP + sc] =
                                    (EHT + t) * NT + tx * 8 + j;
                        }
                    }
                }
            }
            BAR_D();
        }
    }
}

// ============================================================================
// Rescore: exact fp32 dot over ALL candidates, first-index tie-break.
// Overflowed rows (cnt > CAP) -> exact full 4096-scan (cold).
// ============================================================================
__global__ __launch_bounds__(256, 4)
void rescore_kernel(const float* __restrict__ z, float* __restrict__ out_idx)
{
    __shared__ float zsh[256 * 9];   // [c][hwi] pad stride 9

    const int tid = threadIdx.x;
    const int n0  = blockIdx.x * 8;
    const int b   = n0 >> 10;
    const int hw0 = n0 & 1023;
    const float* zb = z + (size_t)b * 262144 + hw0;

    #pragma unroll
    for (int w = 0; w < 8; w++) {
        int idx = tid + w * 256;
        int c = idx >> 3, hwi = idx & 7;
        zsh[c * 9 + hwi] = zb[(size_t)c * 1024 + hwi];
    }
    __syncthreads();

    const int wid = tid >> 5, lane = tid & 31;
    for (int rr = 0; rr < 4; rr++) {
        int lr  = wid * 4 + rr;
        int hwi = lr >> 2;
        int g   = lr & 3;
        int n   = n0 + hwi;
        int row = n * GR + g;
        int cnt = g_cnt[row];
        const float* zr = zsh + (g * 64) * 9 + hwi;

        float bv = -3.0e38f;
        int   be = 0x7FFFFFFF;
        if (cnt > CAP) {
            for (int e = lane; e < NEG; e += 32) {
                const float4* er = reinterpret_cast<const float4*>(
                    g_embn + ((size_t)(g * NEG + e)) * KD);
                float acc = 0.0f;
                #pragma unroll
                for (int kk = 0; kk < 16; kk++) {
                    float4 ev = er[kk];
                    acc = fmaf(zr[(kk * 4 + 0) * 9], ev.x, acc);
                    acc = fmaf(zr[(kk * 4 + 1) * 9], ev.y, acc);
                    acc = fmaf(zr[(kk * 4 + 2) * 9], ev.z, acc);
                    acc = fmaf(zr[(kk * 4 + 3) * 9], ev.w, acc);
                }
                if (acc > bv || (acc == bv && e < be)) { bv = acc; be = e; }
            }
        } else {
            for (int base = 0; base < cnt; base += 32) {
                int c = base + lane;
                if (c < cnt) {
                    int e = g_cand[(size_t)row * CAP + c];
                    const float4* er = reinterpret_cast<const float4*>(
                        g_embn + ((size_t)(g * NEG + e)) * KD);
                    float acc = 0.0f;
                    #pragma unroll
                    for (int kk = 0; kk < 16; kk++) {
                        float4 ev = er[kk];
                        acc = fmaf(zr[(kk * 4 + 0) * 9], ev.x, acc);
                        acc = fmaf(zr[(kk * 4 + 1) * 9], ev.y, acc);
                        acc = fmaf(zr[(kk * 4 + 2) * 9], ev.z, acc);
                        acc = fmaf(zr[(kk * 4 + 3) * 9], ev.w, acc);
                    }
                    if (acc > bv || (acc == bv && e < be)) { bv = acc; be = e; }
                }
            }
        }
        unsigned u = __float_as_uint(bv);
        u = ((int)u < 0) ? ~u : (u | 0x80000000u);
        unsigned m = __reduce_max_sync(0xffffffffu, u);
        unsigned bidm = (u == m) ? (unsigned)be : 0xFFFFFFFFu;
        unsigned bi = __reduce_min_sync(0xffffffffu, bidm);
        if (lane == 0) {
            g_idx[row] = (int)bi;
            out_idx[row] = (float)bi;
        }
    }
}

// ============================================================================
// quant (float4): out[b, g*64+c, hw..hw+3] gathered from embn
// ============================================================================
__global__ void quant_kernel(float* __restrict__ out)
{
    int i = blockIdx.x * blockDim.x + threadIdx.x;   // 0..1048575
    int o = i * 4;
    int hw = o & 1023;
    int ch = (o >> 10) & 255;
    int b  = o >> 18;
    int gg = ch >> 6, c = ch & 63;
    int n0 = (b << 10) + hw;
    const float* eb = g_embn + (size_t)(gg << 12) * KD + c;
    float4 r;
    r.x = eb[(size_t)g_idx[(n0 + 0) * GR + gg] * KD];
    r.y = eb[(size_t)g_idx[(n0 + 1) * GR + gg] * KD];
    r.z = eb[(size_t)g_idx[(n0 + 2) * GR + gg] * KD];
    r.w = eb[(size_t)g_idx[(n0 + 3) * GR + gg] * KD];
    *reinterpret_cast<float4*>(out + o) = r;
}

// one-hot of idx[:, 3] + histogram
__global__ void scatter_kernel(float* __restrict__ out_me)
{
    int n = blockIdx.x * blockDim.x + threadIdx.x;
    if (n >= NQ) return;
    int v = g_idx[n * GR + 3];
    out_me[(size_t)n * NEG + v] = 1.0f;
    atomicAdd(&g_hist[v], 1);
}

__global__ void perp_kernel(float* __restrict__ out_p)
{
    __shared__ float red[32];
    int t = threadIdx.x;
    float s = 0.0f;
    for (int i = t; i < NEG; i += 1024) {
        float p = (float)g_hist[i] * (1.0f / 16384.0f);
        s += p * logf(p + 1e-10f);
    }
    #pragma unroll
    for (int m = 16; m >= 1; m >>= 1) s += __shfl_xor_sync(0xffffffffu, s, m);
    if ((t & 31) == 0) red[t >> 5] = s;
    __syncthreads();
    if (t < 32) {
        float x = red[t];
        #pragma unroll
        for (int m = 16; m >= 1; m >>= 1) x += __shfl_xor_sync(0xffffffffu, x, m);
        if (t == 0) out_p[0] = expf(-x);
    }
}

// ============================================================================
// Output layout (fp32, concatenated, 71,368,717 elements):
//   [0, 4194304)            quant
//   [4194304, +12)          vq_loss(4) commit_loss(4) codebook_usage(4) = zeros
//   [4194316]               perplexity
//   [4194317, +16384*4096)  min_encodings (zeroed inside vq_dual_kernel)
//   [71303181, +65536)      idx (cast to float)
// ============================================================================
extern "C" void kernel_launch(void* const* d_in, const int* in_sizes, int n_in,
                              void* d_out, int out_size)
{
    const float* z   = (const float*)d_in[0];
    const float* emb = (const float*)d_in[1];
    float* out = (float*)d_out;

    const size_t QUANT   = QUANT_SZ;                          // 4194304
    const size_t PERP    = QUANT + 12;
    const size_t ME_OFF  = ME_OFFC;                           // 4194317
    const size_t ME_SZ   = (size_t)NQ * NEG;                  // 67108864
    const size_t IDX_OFF = ME_OFF + ME_SZ;                    // 71303181

    const int SMEM = 76800;
    cudaFuncSetAttribute(vq_dual_kernel,
                         cudaFuncAttributeMaxDynamicSharedMemorySize, SMEM);

    // only losses + perplexity slot (13 floats); min_encodings zeroed in-kernel
    cudaMemsetAsync(out + QUANT, 0, 13 * sizeof(float));

    embprep_kernel<<<2048, 256>>>(emb);

    vq_dual_kernel<<<512, 512, SMEM>>>(z, out);

    rescore_kernel<<<NQ / 8, 256>>>(z, out + IDX_OFF);

    quant_kernel<<<4096, 256>>>(out);
    scatter_kernel<<<64, 256>>>(out + ME_OFF);
    perp_kernel<<<1, 1024>>>(out + PERP);
}

// round 13
// speedup vs baseline: 1.8437x; 1.8437x over previous
#include <cuda_runtime.h>
#include <cuda_fp16.h>
#include <cstdint>

// Problem constants
#define NQ      16384      // B*H*W
#define NEG     4096       // embeddings per group
#define GR      4
#define KD      64         // embedding dim
#define TQ      128        // queries per block
#define NT      128        // e per tile
#define NTILES  32         // tiles per group
#define CAP     64         // candidate capacity per row

#define QUANT_SZ 4194304ULL
#define ME_OFFC  4194317ULL   // QUANT_SZ + 13 (odd -> unaligned head)
#define IDX_OFFC 71303181ULL  // ME_OFFC + 16384*4096

typedef unsigned long long ull;

// ---- device scratch (static, no allocation) ----
__device__ int      g_idx[NQ * GR];               // final argmax indices
__device__ float    g_embn[NEG * GR * KD];        // normalized embedding (fp32)
__device__ int      g_embh[GR * NTILES * 4096];   // fp16 swizzled 16KB tile images
__device__ int      g_hist[NEG];                  // histogram of idx[:, 3]

// ============================================================================
// PTX helpers (base-target: ldmatrix sm_75+, mma.sync sm_80+)
// ============================================================================
__device__ __forceinline__ uint32_t smem_u32(const void* p) {
    uint32_t a;
    asm("{ .reg .u64 t; cvta.to.shared.u64 t, %1; cvt.u32.u64 %0, t; }"
        : "=r"(a) : "l"(p));
    return a;
}
#define LDSM_X4(r, addr) \
    asm volatile("ldmatrix.sync.aligned.m8n8.x4.shared.b16 {%0,%1,%2,%3}, [%4];" \
        : "=r"((r)[0]), "=r"((r)[1]), "=r"((r)[2]), "=r"((r)[3]) : "r"(addr))

__device__ __forceinline__ void mma16816(float* c, const uint32_t* a,
                                         const uint32_t* b) {
    asm volatile("mma.sync.aligned.m16n8k16.row.col.f32.f16.f16.f32 "
        "{%0,%1,%2,%3}, {%4,%5,%6,%7}, {%8,%9}, {%0,%1,%2,%3};"
        : "+f"(c[0]), "+f"(c[1]), "+f"(c[2]), "+f"(c[3])
        : "r"(a[0]), "r"(a[1]), "r"(a[2]), "r"(a[3]), "r"(b[0]), "r"(b[1]));
}

// ============================================================================
// emb prep (+ hist init folded): normalize rows -> g_embn(fp32); fp16
// XOR-swizzled tile images -> g_embh.  One warp per embedding row.
// ============================================================================
__global__ void embprep_kernel(const float* __restrict__ emb)
{
    int gidx = blockIdx.x * blockDim.x + threadIdx.x;
    if (gidx < NEG) g_hist[gidx] = 0;

    int warp = gidx >> 5;
    int lane = threadIdx.x & 31;
    float2 v = reinterpret_cast<const float2*>(emb + (size_t)warp * KD)[lane];
    float s = v.x * v.x + v.y * v.y;
    #pragma unroll
    for (int m = 16; m >= 1; m >>= 1) s += __shfl_xor_sync(0xffffffffu, s, m);
    float inv = 1.0f / fmaxf(sqrtf(s), 1e-12f);
    float2 o = make_float2(v.x * inv, v.y * inv);
    reinterpret_cast<float2*>(g_embn + (size_t)warp * KD)[lane] = o;

    __half2 h2 = __floats2half2_rn(o.x, o.y);
    int w; memcpy(&w, &h2, 4);
    int g  = warp >> 12;
    int el = warp & 4095;
    int et = el >> 7, er = el & 127;
    int ui = er * 32 + ((((lane >> 2)) ^ (er & 7)) << 2) + (lane & 3);
    g_embh[(size_t)(g * NTILES + et) * 4096 + ui] = w;
}

// ============================================================================
// Fused GEMM + argmax + rescore + quant.  One CTA per (qtile, group),
// grid 512, 256 threads, 2 CTAs/SM.  R8 HMMA core; candidates live in smem;
// after the tile loop the CTA rescores its own rows exactly (fp32) and
// writes idx + its quant slice.  Also streams ME zero-stores.
// Smem: smarg[128]@0 | sred@512 | scnt@576 | swin@1088 | A 16KB@2048 |
//   Bh0@18432 Bh1@34816 (zsh reuses Bh after loop) | scand 32KB@51200.
//   Total 83968.
// ============================================================================
__global__ __launch_bounds__(256, 2)
void vq_fused_kernel(const float* __restrict__ z, float* __restrict__ out)
{
    extern __shared__ __align__(1024) char smem[];
    float* smarg = reinterpret_cast<float*>(smem);            // 128 floats
    float* sred  = reinterpret_cast<float*>(smem + 512);      // 16 floats
    int*   scnt  = reinterpret_cast<int*>(smem + 576);        // 128 ints
    int*   swin  = reinterpret_cast<int*>(smem + 1088);       // 128 ints
    int*   scand = reinterpret_cast<int*>(smem + 51200);      // 128*CAP ints
    uint32_t sbase = smem_u32(smem);
    const uint32_t aA = sbase + 2048;
    const uint32_t aBh[2] = { sbase + 18432, sbase + 34816 };
    int4* sBh4[2] = { reinterpret_cast<int4*>(smem + 18432),
                      reinterpret_cast<int4*>(smem + 34816) };
    float* zsh = reinterpret_cast<float*>(smem + 18432);      // 32KB after loop

    const int tid   = threadIdx.x;
    const int item  = blockIdx.x;
    const int g     = item & 3;
    const int qbase = (item >> 2) * TQ;
    const int b     = qbase >> 10;
    const int hwb   = qbase & 1023;
    const float* zb = z + (size_t)b * 262144 + (size_t)(g * 64) * 1024 + hwb;

    // min_encodings zero-slice for this CTA: 131072 floats
    const size_t S = ME_OFFC + (size_t)item * 131072;
    float4* me4 = reinterpret_cast<float4*>(out + S + 3);   // 16B aligned

    // ---- prologue: build A tile (fp16, swizzled) + per-row margin ----
    {
        const int q  = tid & 127;
        const int ph = tid >> 7;                 // c-pairs ph*16..+15
        __half2* A2 = reinterpret_cast<__half2*>(smem + 2048);
        float n2 = 0.0f;
        #pragma unroll
        for (int i = 0; i < 16; i++) {
            int c = (ph * 16 + i) * 2;
            float v0 = zb[(size_t)c * 1024 + q];
            float v1 = zb[(size_t)(c + 1) * 1024 + q];
            n2 += v0 * v0 + v1 * v1;
            int ui = q * 32 + (((c >> 3) ^ (q & 7)) << 2) + ((c & 7) >> 1);
            A2[ui] = __floats2half2_rn(v0, v1);
        }
        if (ph == 0) smarg[q] = n2;
        if (tid < 128) scnt[tid] = 0;
        // preload B(0)
        {
            const int4* s4 = reinterpret_cast<const int4*>(
                g_embh + (size_t)(g * NTILES) * 4096);
            #pragma unroll
            for (int i = 0; i < 4; i++) sBh4[0][tid + i * 256] = s4[tid + i * 256];
        }
        __syncthreads();
        if (ph == 1) smarg[q] = 0.006f * sqrtf(smarg[q] + n2);
        __syncthreads();
    }

    const int w  = tid >> 5;
    const int l  = tid & 31;
    const int qw = (w & 3) * 32;
    const int ew = (w >> 2) * 64;

    float rm[4], marg[4];
    int   rloc[4];
    #pragma unroll
    for (int qb = 0; qb < 2; qb++)
        #pragma unroll
        for (int h = 0; h < 2; h++) {
            int slot = qb * 2 + h;
            int rq = qw + qb * 16 + (l >> 2) + h * 8;
            rm[slot]   = -3.0e38f;
            marg[slot] = smarg[rq];
            rloc[slot] = rq;
        }

    const int4* esrc = reinterpret_cast<const int4*>(
        g_embh + (size_t)(g * NTILES) * 4096);

    if (tid < 3)  out[S + tid] = 0.0f;        // ME unaligned head
    if (tid == 3) out[S + 131071] = 0.0f;     // ME tail float

    for (int t = 0; t < NTILES; t++) {
        // prefetch next B tile into the other buffer
        if (t + 1 < NTILES) {
            const int4* s4 = esrc + (size_t)(t + 1) * 1024;
            int4* d4 = sBh4[(t + 1) & 1];
            #pragma unroll
            for (int i = 0; i < 4; i++) d4[tid + i * 256] = s4[tid + i * 256];
        }
        // streamed zero-stores for min_encodings slice
        {
            const float4 z4 = make_float4(0.f, 0.f, 0.f, 0.f);
            #pragma unroll
            for (int i = 0; i < 4; i++) {
                int j = t * 1024 + i * 256 + tid;
                if (j < 32767) me4[j] = z4;
            }
        }

        float acc[2][8][4];
        #pragma unroll
        for (int qb = 0; qb < 2; qb++)
            #pragma unroll
            for (int eb = 0; eb < 8; eb++)
                #pragma unroll
                for (int j = 0; j < 4; j++) acc[qb][eb][j] = 0.0f;

        const uint32_t base = aBh[t & 1];
        #pragma unroll
        for (int ks = 0; ks < 4; ks++) {
            uint32_t RA[2][4];
            #pragma unroll
            for (int qb = 0; qb < 2; qb++) {
                int row = qw + qb * 16 + (l & 15);
                int blk = ks * 2 + (l >> 4);
                LDSM_X4(RA[qb], aA + row * 128 + ((blk ^ (row & 7)) << 4));
            }
            uint32_t RB[4][4];
            #pragma unroll
            for (int ebp = 0; ebp < 4; ebp++) {
                int row = ew + ebp * 16 + (l & 7) + ((l >> 4) << 3);
                int blk = ks * 2 + ((l >> 3) & 1);
                LDSM_X4(RB[ebp], base + row * 128 + ((blk ^ (row & 7)) << 4));
            }
            #pragma unroll
            for (int qb = 0; qb < 2; qb++)
                #pragma unroll
                for (int eb = 0; eb < 8; eb++)
                    mma16816(acc[qb][eb], RA[qb], &RB[eb >> 1][(eb & 1) * 2]);
        }

        // ---- epilogue: half2 max tree + gated scan, smem candidate push ----
        #pragma unroll
        for (int qb = 0; qb < 2; qb++)
            #pragma unroll
            for (int h = 0; h < 2; h++) {
                const int slot = qb * 2 + h;
                __half2 m2 = __floats2half2_rn(acc[qb][0][h * 2],
                                               acc[qb][0][h * 2 + 1]);
                #pragma unroll
                for (int eb = 1; eb < 8; eb++)
                    m2 = __hmax2(m2, __floats2half2_rn(acc[qb][eb][h * 2],
                                                       acc[qb][eb][h * 2 + 1]));
                float mx = __half2float(__hmax(__low2half(m2), __high2half(m2)));
                mx = fmaxf(mx, __shfl_xor_sync(0xffffffffu, mx, 1));
                mx = fmaxf(mx, __shfl_xor_sync(0xffffffffu, mx, 2));
                if (mx > rm[slot]) rm[slot] = mx;
                const float thr = rm[slot] - marg[slot];
                if (__any_sync(0xffffffffu, mx >= thr - 0.015f)) {
                    #pragma unroll
                    for (int eb = 0; eb < 8; eb++)
                        #pragma unroll
                        for (int j = 0; j < 2; j++) {
                            float vv = acc[qb][eb][h * 2 + j];
                            if (vv >= thr) {
                                int sc = atomicAdd(&scnt[rloc[slot]], 1);
                                if (sc < CAP)
                                    scand[rloc[slot] * CAP + sc] =
                                        t * NT + ew + eb * 8 + (l & 3) * 2 + j;
                            }
                        }
                }
            }
        __syncthreads();
    }

    // ======================= fused rescore tail =======================
    // reload fp32 z rows into the (now dead) B buffers: zsh[c*128+q]
    #pragma unroll
    for (int i = 0; i < 32; i++) {
        int idx = tid + i * 256;       // 8192 = 64c * 128q
        int c = idx >> 7, q2 = idx & 127;
        zsh[c * 128 + q2] = zb[(size_t)c * 1024 + q2];
    }
    __syncthreads();

    // warp w rescores rows w*16 .. w*16+15 (exact fp32, first-index ties)
    const float* embg = g_embn + (size_t)g * NEG * KD;
    for (int r16 = 0; r16 < 16; r16++) {
        const int rq = w * 16 + r16;
        const int cnt = scnt[rq];
        float bv = -3.0e38f;
        int   be = 0x7FFFFFFF;
        if (cnt > CAP) {
            for (int e = l; e < NEG; e += 32) {
                const float4* er = reinterpret_cast<const float4*>(
                    embg + (size_t)e * KD);
                float acc = 0.0f;
                #pragma unroll
                for (int kk = 0; kk < 16; kk++) {
                    float4 ev = er[kk];
                    acc = fmaf(zsh[(kk * 4 + 0) * 128 + rq], ev.x, acc);
                    acc = fmaf(zsh[(kk * 4 + 1) * 128 + rq], ev.y, acc);
                    acc = fmaf(zsh[(kk * 4 + 2) * 128 + rq], ev.z, acc);
                    acc = fmaf(zsh[(kk * 4 + 3) * 128 + rq], ev.w, acc);
                }
                if (acc > bv || (acc == bv && e < be)) { bv = acc; be = e; }
            }
        } else {
            for (int cbase = 0; cbase < cnt; cbase += 32) {
                int c = cbase + l;
                if (c < cnt) {
                    int e = scand[rq * CAP + c];
                    const float4* er = reinterpret_cast<const float4*>(
                        embg + (size_t)e * KD);
                    float acc = 0.0f;
                    #pragma unroll
                    for (int kk = 0; kk < 16; kk++) {
                        float4 ev = er[kk];
                        acc = fmaf(zsh[(kk * 4 + 0) * 128 + rq], ev.x, acc);
                        acc = fmaf(zsh[(kk * 4 + 1) * 128 + rq], ev.y, acc);
                        acc = fmaf(zsh[(kk * 4 + 2) * 128 + rq], ev.z, acc);
                        acc = fmaf(zsh[(kk * 4 + 3) * 128 + rq], ev.w, acc);
                    }
                    if (acc > bv || (acc == bv && e < be)) { bv = acc; be = e; }
                }
            }
        }
        unsigned u = __float_as_uint(bv);
        u = ((int)u < 0) ? ~u : (u | 0x80000000u);
        unsigned m = __reduce_max_sync(0xffffffffu, u);
        unsigned bidm = (u == m) ? (unsigned)be : 0xFFFFFFFFu;
        unsigned bi = __reduce_min_sync(0xffffffffu, bidm);
        if (l == 0) {
            swin[rq] = (int)bi;
            int n = qbase + rq;
            g_idx[n * GR + g] = (int)bi;
            out[IDX_OFFC + (size_t)n * GR + g] = (float)bi;
        }
    }
    __syncthreads();

    // ======================= fused quant tail =======================
    // out[b, g*64+c, hwb+q] = embn[g*4096 + swin[q], c]; coalesced stores.
    {
        const int q  = tid & 127;
        const int ph = tid >> 7;                 // c = ph*32 .. +31
        const float* er = embg + (size_t)swin[q] * KD;
        float* oq = out + (size_t)b * 262144 + (size_t)(g * 64) * 1024 + hwb + q;
        #pragma unroll
        for (int i = 0; i < 32; i++) {
            int c = ph * 32 + i;
            oq[(size_t)c * 1024] = er[c];
        }
    }
}

// one-hot of idx[:, 3] + histogram
__global__ void scatter_kernel(float* __restrict__ out_me)
{
    int n = blockIdx.x * blockDim.x + threadIdx.x;
    if (n >= NQ) return;
    int v = g_idx[n * GR + 3];
    out_me[(size_t)n * NEG + v] = 1.0f;
    atomicAdd(&g_hist[v], 1);
}

__global__ void perp_kernel(float* __restrict__ out_p)
{
    __shared__ float red[32];
    int t = threadIdx.x;
    float s = 0.0f;
    for (int i = t; i < NEG; i += 1024) {
        float p = (float)g_hist[i] * (1.0f / 16384.0f);
        s += p * logf(p + 1e-10f);
    }
    #pragma unroll
    for (int m = 16; m >= 1; m >>= 1) s += __shfl_xor_sync(0xffffffffu, s, m);
    if ((t & 31) == 0) red[t >> 5] = s;
    __syncthreads();
    if (t < 32) {
        float x = red[t];
        #pragma unroll
        for (int m = 16; m >= 1; m >>= 1) x += __shfl_xor_sync(0xffffffffu, x, m);
        if (t == 0) out_p[0] = expf(-x);
    }
}

// ============================================================================
// Output layout (fp32, concatenated, 71,368,717 elements):
//   [0, 4194304)            quant      (written inside vq_fused_kernel)
//   [4194304, +12)          losses = zeros
//   [4194316]               perplexity
//   [4194317, +16384*4096)  min_encodings (zeroed inside vq_fused_kernel)
//   [71303181, +65536)      idx (written inside vq_fused_kernel)
// ============================================================================
extern "C" void kernel_launch(void* const* d_in, const int* in_sizes, int n_in,
                              void* d_out, int out_size)
{
    const float* z   = (const float*)d_in[0];
    const float* emb = (const float*)d_in[1];
    float* out = (float*)d_out;

    const size_t QUANT = QUANT_SZ;
    const size_t PERP  = QUANT + 12;

    const int SMEM = 83968;
    cudaFuncSetAttribute(vq_fused_kernel,
                         cudaFuncAttributeMaxDynamicSharedMemorySize, SMEM);

    // only losses + perplexity slot (13 floats)
    cudaMemsetAsync(out + QUANT, 0, 13 * sizeof(float));

    embprep_kernel<<<2048, 256>>>(emb);

    vq_fused_kernel<<<512, 256, SMEM>>>(z, out);

    scatter_kernel<<<64, 256>>>(out + ME_OFFC);
    perp_kernel<<<1, 1024>>>(out + PERP);
}